// round 5
// baseline (speedup 1.0000x reference)
#include <cuda_runtime.h>
#include <cuda_bf16.h>
#include <cstdint>

// ============================================================================
// Problem constants
// ============================================================================
#define T_TOK   8192          // B*S tokens
#define HDIM    2048
#define NEXP    8
#define NSLOTS  17408         // 2*T + 8*128 padding
#define MAX_TILES 136
#define KSTEPS  64            // K=2048 / 32 per k-step

// ============================================================================
// PTX helpers — family-portable only (mma.sync / ldmatrix / cp.async)
// ============================================================================
__device__ __forceinline__ uint32_t smem_to_u32(const void* p) {
    uint32_t a;
    asm("{ .reg .u64 t; cvta.to.shared.u64 t, %1; cvt.u32.u64 %0, t; }"
        : "=r"(a) : "l"(p));
    return a;
}

#define CP_ASYNC16(smem, gmem) \
    asm volatile("cp.async.cg.shared.global [%0], [%1], 16;" \
        :: "r"(smem), "l"(gmem))
#define CP_COMMIT() asm volatile("cp.async.commit_group;" ::: "memory")
#define CP_WAIT2()  asm volatile("cp.async.wait_group 2;" ::: "memory")

__device__ __forceinline__ void ldsm_x4(uint32_t* r, uint32_t addr) {
    asm volatile("ldmatrix.sync.aligned.m8n8.x4.shared.b16 {%0,%1,%2,%3}, [%4];"
        : "=r"(r[0]), "=r"(r[1]), "=r"(r[2]), "=r"(r[3]) : "r"(addr));
}

// m16n8k32 s8 IMMA, s32 accumulate
__device__ __forceinline__ void imma16832(int* d, const uint32_t* a,
                                          const uint32_t* b) {
    asm volatile(
        "mma.sync.aligned.m16n8k32.row.col.s32.s8.s8.s32 "
        "{%0,%1,%2,%3}, {%4,%5,%6,%7}, {%8,%9}, {%0,%1,%2,%3};"
        : "+r"(d[0]), "+r"(d[1]), "+r"(d[2]), "+r"(d[3])
        : "r"(a[0]), "r"(a[1]), "r"(a[2]), "r"(a[3]), "r"(b[0]), "r"(b[1]));
}

// ============================================================================
// Device scratch
// ============================================================================
__device__ int    g_count[NEXP];
__device__ int    g_cursor[NEXP];
__device__ int    g_base[NEXP];
__device__ int    g_tile_expert[MAX_TILES];
__device__ int    g_tile_mbase[MAX_TILES];
__device__ int    g_num_tiles;
__device__ int    g_topi[T_TOK * 2];
__device__ float  g_topw[T_TOK * 2];
__device__ int    g_slot_token[NSLOTS];    // zero-init; padding rows unread
__device__ float  g_slot_w[NSLOTS];
__device__ int    g_tok_slot[T_TOK * 2];

__device__ int8_t g_x1[(size_t)NSLOTS * HDIM];           // 36 MB
__device__ int8_t g_x2[(size_t)NSLOTS * HDIM];           // 36 MB
__device__ int8_t g_w1[(size_t)NEXP * HDIM * HDIM];      // 34 MB
__device__ int8_t g_w2[(size_t)NEXP * HDIM * HDIM];      // 34 MB
__device__ float  g_sx[NSLOTS];                          // per-row dequant scale
__device__ float  g_sw[NEXP * HDIM];
__device__ float  g_ybuf[(size_t)NSLOTS * HDIM];         // 143 MB

// ============================================================================
// K0: reset counters
// ============================================================================
__global__ void moe_init_kernel() {
    int tid = threadIdx.x;
    if (tid < NEXP) { g_count[tid] = 0; g_cursor[tid] = 0; }
}

// ============================================================================
// K1: router — logits + top-2 normalized weights. One warp per token.
// ============================================================================
__global__ void moe_router_kernel(const float* __restrict__ x,
                                  const float* __restrict__ gw,
                                  float* __restrict__ logits_out) {
    int warp = (blockIdx.x * blockDim.x + threadIdx.x) >> 5;
    int lane = threadIdx.x & 31;
    if (warp >= T_TOK) return;
    const float4* xr = (const float4*)(x + (size_t)warp * HDIM);
    float acc[NEXP];
#pragma unroll
    for (int e = 0; e < NEXP; e++) acc[e] = 0.f;
    for (int i = lane; i < HDIM / 4; i += 32) {
        float4 xv = xr[i];
#pragma unroll
        for (int e = 0; e < NEXP; e++) {
            float4 gv = ((const float4*)(gw + e * HDIM))[i];
            acc[e] += xv.x * gv.x + xv.y * gv.y + xv.z * gv.z + xv.w * gv.w;
        }
    }
#pragma unroll
    for (int e = 0; e < NEXP; e++)
#pragma unroll
        for (int off = 16; off; off >>= 1)
            acc[e] += __shfl_xor_sync(0xFFFFFFFFu, acc[e], off);
    if (lane == 0) {
#pragma unroll
        for (int e = 0; e < NEXP; e++) logits_out[warp * NEXP + e] = acc[e];
        int i1 = 0; float l1 = acc[0];
#pragma unroll
        for (int e = 1; e < NEXP; e++) if (acc[e] > l1) { l1 = acc[e]; i1 = e; }
        int i2 = -1; float l2 = -3.4e38f;
#pragma unroll
        for (int e = 0; e < NEXP; e++)
            if (e != i1 && acc[e] > l2) { l2 = acc[e]; i2 = e; }
        float ex = expf(l2 - l1);
        float w1 = 1.0f / (1.0f + ex);
        float w2 = ex / (1.0f + ex);
        g_topi[warp * 2 + 0] = i1;  g_topw[warp * 2 + 0] = w1;
        g_topi[warp * 2 + 1] = i2;  g_topw[warp * 2 + 1] = w2;
        atomicAdd(&g_count[i1], 1);
        atomicAdd(&g_count[i2], 1);
    }
}

// ============================================================================
// K2: serial scan — padded slot bases + tile map
// ============================================================================
__global__ void moe_scan_kernel() {
    if (threadIdx.x == 0 && blockIdx.x == 0) {
        int run = 0, nt = 0;
        for (int e = 0; e < NEXP; e++) {
            g_base[e] = run;
            int c = g_count[e];
            int tiles = (c + 127) >> 7;
            for (int t = 0; t < tiles; t++) {
                g_tile_expert[nt] = e;
                g_tile_mbase[nt]  = run + t * 128;
                nt++;
            }
            run += tiles << 7;
        }
        g_num_tiles = nt;
    }
}

// ============================================================================
// K3: scatter tokens into per-expert slot lists
// ============================================================================
__global__ void moe_assign_kernel() {
    int t = blockIdx.x * blockDim.x + threadIdx.x;
    if (t >= T_TOK) return;
#pragma unroll
    for (int k = 0; k < 2; k++) {
        int e = g_topi[t * 2 + k];
        int pos = atomicAdd(&g_cursor[e], 1);
        int slot = g_base[e] + pos;
        g_slot_token[slot] = t;
        g_slot_w[slot] = g_topw[t * 2 + k];
        g_tok_slot[t * 2 + k] = slot;
    }
}

// ============================================================================
// K4: merged quantize — x (slot-gathered) and expert weights -> two-level s8.
// One block per row: row max-abs -> scale, then q = v*127/scale,
// level1 = rint(q), level2 = rint((q-level1)*254).  v ~ sx*(q1 + q2/254).
// ============================================================================
__global__ void moe_quant_kernel(const float* __restrict__ x,
                                 const float* __restrict__ ew) {
    __shared__ float red[8];
    __shared__ float s_scale;
    int b = blockIdx.x;
    int tid = threadIdx.x, lane = tid & 31, wid = tid >> 5;

    const float* src;
    int8_t *d1, *d2;
    float* sdst;
    if (b < NSLOTS) {
        int tok = g_slot_token[b];
        src  = x + (size_t)tok * HDIM;
        d1   = g_x1 + (size_t)b * HDIM;
        d2   = g_x2 + (size_t)b * HDIM;
        sdst = g_sx + b;
    } else {
        int r = b - NSLOTS;                     // e*HDIM + n row of weights
        src  = ew + (size_t)r * HDIM;
        d1   = g_w1 + (size_t)r * HDIM;
        d2   = g_w2 + (size_t)r * HDIM;
        sdst = g_sw + r;
    }

    float4 v0 = ((const float4*)src)[tid * 2];
    float4 v1 = ((const float4*)src)[tid * 2 + 1];
    float m = fabsf(v0.x);
    m = fmaxf(m, fabsf(v0.y)); m = fmaxf(m, fabsf(v0.z));
    m = fmaxf(m, fabsf(v0.w)); m = fmaxf(m, fabsf(v1.x));
    m = fmaxf(m, fabsf(v1.y)); m = fmaxf(m, fabsf(v1.z));
    m = fmaxf(m, fabsf(v1.w));
#pragma unroll
    for (int off = 16; off; off >>= 1)
        m = fmaxf(m, __shfl_xor_sync(0xFFFFFFFFu, m, off));
    if (lane == 0) red[wid] = m;
    __syncthreads();
    if (tid == 0) {
        float mm = red[0];
#pragma unroll
        for (int i = 1; i < 8; i++) mm = fmaxf(mm, red[i]);
        mm = fmaxf(mm, 1e-20f);
        s_scale = mm;
        *sdst = mm * (1.0f / 127.0f);
    }
    __syncthreads();
    float inv = 127.0f / s_scale;

    float v[8] = {v0.x, v0.y, v0.z, v0.w, v1.x, v1.y, v1.z, v1.w};
    uint32_t p1[2] = {0, 0}, p2[2] = {0, 0};
#pragma unroll
    for (int i = 0; i < 8; i++) {
        float q = v[i] * inv;
        int q1 = __float2int_rn(q);
        float r = q - (float)q1;
        int q2 = __float2int_rn(r * 254.0f);
        p1[i >> 2] |= ((uint32_t)q1 & 0xFFu) << ((i & 3) * 8);
        p2[i >> 2] |= ((uint32_t)q2 & 0xFFu) << ((i & 3) * 8);
    }
    ((uint2*)(d1))[tid] = make_uint2(p1[0], p1[1]);
    ((uint2*)(d2))[tid] = make_uint2(p2[0], p2[1]);
}

// ============================================================================
// K5: grouped GEMM — 128x128x2048, two-level s8 IMMA (3 terms),
// 512 threads (4x4 warps, 32x32 warp tile), 4-stage cp.async, 48B rows.
// out = sx[row]*sw[col]*slotw[row] * (acc1 + acc23/254)
// ============================================================================
#define RSB       48                          // padded row bytes (16-aligned)
#define MAT_B     (128 * RSB)                 // 6144 B per matrix
#define STAGE_B   (4 * MAT_B)                 // 24576 B (A1,A2,B1,B2)
#define NSTAGE    4
#define SMEM_DYN  (1024 + NSTAGE * STAGE_B)   // 99328 B

__global__ void __launch_bounds__(512, 1)
moe_gemm_kernel() {
    int tile = blockIdx.y;
    if (tile >= g_num_tiles) return;
    int n0    = blockIdx.x * 128;
    int e     = g_tile_expert[tile];
    int mbase = g_tile_mbase[tile];

    extern __shared__ char dsm[];
    float* s_fr = (float*)dsm;                // 128: sx*slotw per row
    float* s_fc = (float*)(dsm + 512);        // 128: sw per col
    uint32_t st0 = smem_to_u32(dsm) + 1024;

    int tid = threadIdx.x, lane = tid & 31, wid = tid >> 5;
    int wm = wid >> 2, wn = wid & 3;          // 4 x 4 warp grid

    if (tid < 128) {
        s_fr[tid] = g_sx[mbase + tid] * g_slot_w[mbase + tid];
        s_fc[tid] = g_sw[e * HDIM + n0 + tid];
    }

    const int8_t* A1g = g_x1 + (size_t)mbase * HDIM;
    const int8_t* A2g = g_x2 + (size_t)mbase * HDIM;
    const int8_t* B1g = g_w1 + ((size_t)e * HDIM + n0) * HDIM;
    const int8_t* B2g = g_w2 + ((size_t)e * HDIM + n0) * HDIM;

    // fill stage: 1024 x 16B chunks over 512 threads (2 per thread)
    auto fill = [&](int stage, int kt) {
        uint32_t sbase = st0 + stage * STAGE_B;
        int k0 = kt * 32;
#pragma unroll
        for (int i = 0; i < 2; i++) {
            int cid = tid + i * 512;
            int mat = cid >> 8;               // 0=A1,1=A2,2=B1,3=B2
            int win = cid & 255;
            int rr  = win >> 1;
            int cc  = win & 1;
            const int8_t* gb = (mat == 0) ? A1g : (mat == 1) ? A2g
                             : (mat == 2) ? B1g : B2g;
            const int8_t* gp = gb + (size_t)rr * HDIM + k0 + cc * 16;
            uint32_t sm = sbase + mat * MAT_B + rr * RSB + cc * 16;
            CP_ASYNC16(sm, gp);
        }
    };

    fill(0, 0); CP_COMMIT();
    fill(1, 1); CP_COMMIT();
    fill(2, 2); CP_COMMIT();

    int acc1[2][4][4], acc23[2][4][4];
#pragma unroll
    for (int a = 0; a < 2; a++)
#pragma unroll
        for (int b = 0; b < 4; b++)
#pragma unroll
            for (int c = 0; c < 4; c++) { acc1[a][b][c] = 0; acc23[a][b][c] = 0; }

    for (int kt = 0; kt < KSTEPS; kt++) {
        CP_WAIT2();
        __syncthreads();
        int nxt = kt + 3;
        if (nxt < KSTEPS) fill(nxt & 3, nxt);
        CP_COMMIT();

        uint32_t sbase = st0 + (kt & 3) * STAGE_B;
        uint32_t sA1 = sbase, sA2 = sbase + MAT_B;
        uint32_t sB1 = sbase + 2 * MAT_B, sB2 = sbase + 3 * MAT_B;

        // A frags: 16x32 s8 per mi, ldmatrix.x4 on b16 view
        uint32_t a1[2][4], a2[2][4];
#pragma unroll
        for (int mi = 0; mi < 2; mi++) {
            uint32_t ad = (uint32_t)((wm * 32 + mi * 16 + (lane & 15)) * RSB
                                     + (lane >> 4) * 16);
            ldsm_x4(a1[mi], sA1 + ad);
            ldsm_x4(a2[mi], sA2 + ad);
        }
        // B frags: per jj covers two n8 groups (16 n-rows x 32 k)
        uint32_t b1[4][2], b2[4][2];
#pragma unroll
        for (int jj = 0; jj < 2; jj++) {
            uint32_t bd = (uint32_t)((wn * 32 + jj * 16 + ((lane >> 4) << 3)
                                      + (lane & 7)) * RSB
                                     + ((lane >> 3) & 1) * 16);
            uint32_t t[4];
            ldsm_x4(t, sB1 + bd);
            b1[jj * 2][0] = t[0]; b1[jj * 2][1] = t[1];
            b1[jj * 2 + 1][0] = t[2]; b1[jj * 2 + 1][1] = t[3];
            ldsm_x4(t, sB2 + bd);
            b2[jj * 2][0] = t[0]; b2[jj * 2][1] = t[1];
            b2[jj * 2 + 1][0] = t[2]; b2[jj * 2 + 1][1] = t[3];
        }
        // term-major: acc reuse distance 8 MMAs
#pragma unroll
        for (int mi = 0; mi < 2; mi++)
#pragma unroll
            for (int j = 0; j < 4; j++)
                imma16832(acc1[mi][j], a1[mi], b1[j]);
#pragma unroll
        for (int mi = 0; mi < 2; mi++)
#pragma unroll
            for (int j = 0; j < 4; j++)
                imma16832(acc23[mi][j], a1[mi], b2[j]);
#pragma unroll
        for (int mi = 0; mi < 2; mi++)
#pragma unroll
            for (int j = 0; j < 4; j++)
                imma16832(acc23[mi][j], a2[mi], b1[j]);
    }
    __syncthreads();

    // epilogue: dequant + combine weight, write to ybuf
#pragma unroll
    for (int mi = 0; mi < 2; mi++) {
        int r0 = wm * 32 + mi * 16 + (lane >> 2);
        float f0 = s_fr[r0], f1 = s_fr[r0 + 8];
        size_t o0 = (size_t)(mbase + r0) * HDIM + n0;
#pragma unroll
        for (int j = 0; j < 4; j++) {
            int c = wn * 32 + j * 8 + (lane & 3) * 2;
            float fc0 = s_fc[c], fc1 = s_fc[c + 1];
            float s00 = (float)acc1[mi][j][0] + (float)acc23[mi][j][0] * (1.f/254.f);
            float s01 = (float)acc1[mi][j][1] + (float)acc23[mi][j][1] * (1.f/254.f);
            float s10 = (float)acc1[mi][j][2] + (float)acc23[mi][j][2] * (1.f/254.f);
            float s11 = (float)acc1[mi][j][3] + (float)acc23[mi][j][3] * (1.f/254.f);
            *(float2*)(g_ybuf + o0 + c) =
                make_float2(s00 * f0 * fc0, s01 * f0 * fc1);
            *(float2*)(g_ybuf + o0 + (size_t)8 * HDIM + c) =
                make_float2(s10 * f1 * fc0, s11 * f1 * fc1);
        }
    }
}

// ============================================================================
// K6: combine — out[t] = ybuf[slot0(t)] + ybuf[slot1(t)]
// ============================================================================
__global__ void moe_combine_kernel(float* __restrict__ out) {
    int i = blockIdx.x * blockDim.x + threadIdx.x;
    int t  = i >> 9;
    int h4 = i & 511;
    int s0 = g_tok_slot[2 * t + 0];
    int s1 = g_tok_slot[2 * t + 1];
    float4 a = *(const float4*)(g_ybuf + (size_t)s0 * HDIM + h4 * 4);
    float4 b = *(const float4*)(g_ybuf + (size_t)s1 * HDIM + h4 * 4);
    float4 o;
    o.x = a.x + b.x; o.y = a.y + b.y; o.z = a.z + b.z; o.w = a.w + b.w;
    ((float4*)out)[i] = o;
}

// ============================================================================
// Launch
// ============================================================================
extern "C" void kernel_launch(void* const* d_in, const int* in_sizes, int n_in,
                              void* d_out, int out_size) {
    const float* x  = (const float*)d_in[0];   // hidden_states [T, H]
    const float* gw = (const float*)d_in[1];   // gate_w [E, H]
    const float* ew = (const float*)d_in[2];   // expert_w [E, H, H]
    float* out    = (float*)d_out;             // [T, H]
    float* logits = out + (size_t)T_TOK * HDIM;

    cudaFuncSetAttribute(moe_gemm_kernel,
                         cudaFuncAttributeMaxDynamicSharedMemorySize, SMEM_DYN);

    moe_init_kernel<<<1, 32>>>();
    moe_router_kernel<<<(T_TOK * 32) / 256, 256>>>(x, gw, logits);
    moe_scan_kernel<<<1, 32>>>();
    moe_assign_kernel<<<T_TOK / 256, 256>>>();
    moe_quant_kernel<<<NSLOTS + NEXP * HDIM, 256>>>(x, ew);
    moe_gemm_kernel<<<dim3(16, MAX_TILES), 512, SMEM_DYN>>>();
    moe_combine_kernel<<<(T_TOK * (HDIM / 4)) / 256, 256>>>(out);
}

// round 7
// speedup vs baseline: 2.9491x; 2.9491x over previous
#include <cuda_runtime.h>
#include <cuda_fp16.h>
#include <cstdint>

// ============================================================================
// Problem constants
// ============================================================================
#define T_TOK   8192          // B*S tokens
#define HDIM    2048
#define NEXP    8
#define NSLOTS  17408         // 2*T + 8*128 padding
#define MAX_TILES 136
#define KSTEPS  64            // K=2048 / 32 per k-step

// ============================================================================
// PTX helpers — family-portable only (mma.sync / ldmatrix / cp.async)
// ============================================================================
__device__ __forceinline__ uint32_t smem_to_u32(const void* p) {
    uint32_t a;
    asm("{ .reg .u64 t; cvta.to.shared.u64 t, %1; cvt.u32.u64 %0, t; }"
        : "=r"(a) : "l"(p));
    return a;
}

#define CP_ASYNC16(smem, gmem) \
    asm volatile("cp.async.cg.shared.global [%0], [%1], 16;" \
        :: "r"(smem), "l"(gmem))
#define CP_COMMIT() asm volatile("cp.async.commit_group;" ::: "memory")
#define CP_WAIT2()  asm volatile("cp.async.wait_group 2;" ::: "memory")

__device__ __forceinline__ void ldsm_x4(uint32_t* r, uint32_t addr) {
    asm volatile("ldmatrix.sync.aligned.m8n8.x4.shared.b16 {%0,%1,%2,%3}, [%4];"
        : "=r"(r[0]), "=r"(r[1]), "=r"(r[2]), "=r"(r[3]) : "r"(addr));
}

// m16n8k16 fp16 HMMA, fp32 accumulate
__device__ __forceinline__ void mma16816(float* d, const uint32_t* a,
                                         const uint32_t* b) {
    asm volatile(
        "mma.sync.aligned.m16n8k16.row.col.f32.f16.f16.f32 "
        "{%0,%1,%2,%3}, {%4,%5,%6,%7}, {%8,%9}, {%0,%1,%2,%3};"
        : "+f"(d[0]), "+f"(d[1]), "+f"(d[2]), "+f"(d[3])
        : "r"(a[0]), "r"(a[1]), "r"(a[2]), "r"(a[3]), "r"(b[0]), "r"(b[1]));
}

// SW64 swizzle: XOR byte-offset bits[5:4] with bits[8:7] (row bits for 64B rows)
#define SW64(off) ((off) ^ (((off) >> 3) & 0x30))

// ============================================================================
// Device scratch
// ============================================================================
__device__ int    g_count[NEXP];
__device__ int    g_cursor[NEXP];
__device__ int    g_base[NEXP];
__device__ int    g_tile_expert[MAX_TILES];
__device__ int    g_tile_mbase[MAX_TILES];
__device__ int    g_num_tiles;
__device__ int    g_topi[T_TOK * 2];
__device__ float  g_topw[T_TOK * 2];
__device__ int    g_slot_token[NSLOTS];    // zero-init; stale values stay in
__device__ float  g_slot_w[NSLOTS];        //   [0,T) so always a valid index
__device__ int    g_tok_slot[T_TOK * 2];

__device__ __half g_xh[(size_t)NSLOTS * HDIM];           // 71 MB
__device__ __half g_xu[(size_t)NSLOTS * HDIM];           // 71 MB
__device__ __half g_wh[(size_t)NEXP * HDIM * HDIM];      // 67 MB
__device__ __half g_wv[(size_t)NEXP * HDIM * HDIM];      // 67 MB
__device__ float  g_ybuf[(size_t)NSLOTS * HDIM];         // 143 MB

// ============================================================================
// K0: reset counters
// ============================================================================
__global__ void moe_init_kernel() {
    int tid = threadIdx.x;
    if (tid < NEXP) { g_count[tid] = 0; g_cursor[tid] = 0; }
}

// ============================================================================
// K1: router — logits + top-2 normalized weights. One warp per token.
// ============================================================================
__global__ void moe_router_kernel(const float* __restrict__ x,
                                  const float* __restrict__ gw,
                                  float* __restrict__ logits_out) {
    int warp = (blockIdx.x * blockDim.x + threadIdx.x) >> 5;
    int lane = threadIdx.x & 31;
    if (warp >= T_TOK) return;
    const float4* xr = (const float4*)(x + (size_t)warp * HDIM);
    float acc[NEXP];
#pragma unroll
    for (int e = 0; e < NEXP; e++) acc[e] = 0.f;
    for (int i = lane; i < HDIM / 4; i += 32) {
        float4 xv = xr[i];
#pragma unroll
        for (int e = 0; e < NEXP; e++) {
            float4 gv = ((const float4*)(gw + e * HDIM))[i];
            acc[e] += xv.x * gv.x + xv.y * gv.y + xv.z * gv.z + xv.w * gv.w;
        }
    }
#pragma unroll
    for (int e = 0; e < NEXP; e++)
#pragma unroll
        for (int off = 16; off; off >>= 1)
            acc[e] += __shfl_xor_sync(0xFFFFFFFFu, acc[e], off);
    if (lane == 0) {
#pragma unroll
        for (int e = 0; e < NEXP; e++) logits_out[warp * NEXP + e] = acc[e];
        int i1 = 0; float l1 = acc[0];
#pragma unroll
        for (int e = 1; e < NEXP; e++) if (acc[e] > l1) { l1 = acc[e]; i1 = e; }
        int i2 = -1; float l2 = -3.4e38f;
#pragma unroll
        for (int e = 0; e < NEXP; e++)
            if (e != i1 && acc[e] > l2) { l2 = acc[e]; i2 = e; }
        float ex = expf(l2 - l1);
        float w1 = 1.0f / (1.0f + ex);
        float w2 = ex / (1.0f + ex);
        g_topi[warp * 2 + 0] = i1;  g_topw[warp * 2 + 0] = w1;
        g_topi[warp * 2 + 1] = i2;  g_topw[warp * 2 + 1] = w2;
        atomicAdd(&g_count[i1], 1);
        atomicAdd(&g_count[i2], 1);
    }
}

// ============================================================================
// K2: serial scan — padded slot bases + tile map
// ============================================================================
__global__ void moe_scan_kernel() {
    if (threadIdx.x == 0 && blockIdx.x == 0) {
        int run = 0, nt = 0;
        for (int e = 0; e < NEXP; e++) {
            g_base[e] = run;
            int c = g_count[e];
            int tiles = (c + 127) >> 7;
            for (int t = 0; t < tiles; t++) {
                g_tile_expert[nt] = e;
                g_tile_mbase[nt]  = run + t * 128;
                nt++;
            }
            run += tiles << 7;
        }
        g_num_tiles = nt;
    }
}

// ============================================================================
// K3: scatter tokens into per-expert slot lists
// ============================================================================
__global__ void moe_assign_kernel() {
    int t = blockIdx.x * blockDim.x + threadIdx.x;
    if (t >= T_TOK) return;
#pragma unroll
    for (int k = 0; k < 2; k++) {
        int e = g_topi[t * 2 + k];
        int pos = atomicAdd(&g_cursor[e], 1);
        int slot = g_base[e] + pos;
        g_slot_token[slot] = t;
        g_slot_w[slot] = g_topw[t * 2 + k];
        g_tok_slot[t * 2 + k] = slot;
    }
}

// ============================================================================
// K4: split-convert (Ootomo): x -> (xh, u), 64*w -> (wh, v).  Elementwise.
//   xh = fp16(x);            u = fp16(xh/32 + (x - xh))
//   wh = fp16(64w);          v = fp16(wh/32 + (64w - wh))
// ============================================================================
#define XBLK (NSLOTS * 512 / 256)                 // 34816
#define WBLK (NEXP * HDIM * HDIM / 4 / 256)       // 32768

__device__ __forceinline__ void split2(float a, float b, uint32_t& h,
                                       uint32_t& u) {
    __half2 hh = __floats2half2_rn(a, b);
    float2 hf = __half22float2(hh);
    __half2 uu = __floats2half2_rn(hf.x * 0.03125f + (a - hf.x),
                                   hf.y * 0.03125f + (b - hf.y));
    h = *(uint32_t*)&hh;
    u = *(uint32_t*)&uu;
}

__global__ void moe_convert_kernel(const float* __restrict__ x,
                                   const float* __restrict__ ew) {
    if (blockIdx.x < XBLK) {
        int i = blockIdx.x * 256 + threadIdx.x;
        int slot = i >> 9;
        int j = i & 511;
        int tok = g_slot_token[slot];
        float4 vv = *(const float4*)(x + (size_t)tok * HDIM + j * 4);
        uint32_t h0, u0, h1, u1;
        split2(vv.x, vv.y, h0, u0);
        split2(vv.z, vv.w, h1, u1);
        size_t o = (size_t)slot * 512 + j;
        ((uint2*)g_xh)[o] = make_uint2(h0, h1);
        ((uint2*)g_xu)[o] = make_uint2(u0, u1);
    } else {
        size_t i = (size_t)(blockIdx.x - XBLK) * 256 + threadIdx.x;
        float4 vv = ((const float4*)ew)[i];
        uint32_t h0, u0, h1, u1;
        split2(vv.x * 64.f, vv.y * 64.f, h0, u0);
        split2(vv.z * 64.f, vv.w * 64.f, h1, u1);
        ((uint2*)g_wh)[i] = make_uint2(h0, h1);
        ((uint2*)g_wv)[i] = make_uint2(u0, u1);
    }
}

// ============================================================================
// K5: grouped GEMM — 128x128x2048, fp16 Ootomo 2-term, fp32 acc,
// 256 threads (2x4 warps, 64x32 warp tile), 4-stage cp.async, SW64 rows.
// y = (T1*(31/32) + 32*T2) * slotw / 64
// ============================================================================
#define MAT_B     8192                        // 128 rows x 64B
#define STAGE_B   (4 * MAT_B)                 // 32768 (A1,A2,B1,B2)
#define NSTAGE    4
#define SMEM_DYN  (1024 + NSTAGE * STAGE_B)   // 132096 B

__global__ void __launch_bounds__(256, 1)
moe_gemm_kernel() {
    int tile = blockIdx.y;
    if (tile >= g_num_tiles) return;
    int n0    = blockIdx.x * 128;
    int e     = g_tile_expert[tile];
    int mbase = g_tile_mbase[tile];

    extern __shared__ char dsm[];
    float* s_fr = (float*)dsm;                // 128: slotw/64 per row
    uint32_t st0 = smem_to_u32(dsm) + 1024;

    int tid = threadIdx.x, lane = tid & 31, wid = tid >> 5;
    int wm = wid >> 2, wn = wid & 3;          // 2 x 4 grid, warp 64(M)x32(N)

    if (tid < 128) s_fr[tid] = g_slot_w[mbase + tid] * (1.0f / 64.0f);

    const __half* A1g = g_xh + (size_t)mbase * HDIM;
    const __half* A2g = g_xu + (size_t)mbase * HDIM;
    const __half* B1g = g_wh + ((size_t)e * HDIM + n0) * HDIM;
    const __half* B2g = g_wv + ((size_t)e * HDIM + n0) * HDIM;

    // fill stage: 2048 x 16B chunks over 256 threads (8 per thread)
    auto fill = [&](int stage, int kt) {
        uint32_t sbase = st0 + stage * STAGE_B;
        int k0 = kt * 32;
#pragma unroll
        for (int i = 0; i < 8; i++) {
            int cid = tid + i * 256;
            int mat = cid >> 9;               // 0=A1,1=A2,2=B1,3=B2
            int win = cid & 511;
            int rr  = win >> 2;
            int cc  = win & 3;
            const __half* gb = (mat == 0) ? A1g : (mat == 1) ? A2g
                             : (mat == 2) ? B1g : B2g;
            const __half* gp = gb + (size_t)rr * HDIM + k0 + cc * 8;
            uint32_t sm = sbase + mat * MAT_B
                        + SW64((uint32_t)(rr * 64 + cc * 16));
            CP_ASYNC16(sm, gp);
        }
    };

    fill(0, 0); CP_COMMIT();
    fill(1, 1); CP_COMMIT();
    fill(2, 2); CP_COMMIT();

    float acc1[4][4][4], acc2[4][4][4];
#pragma unroll
    for (int a = 0; a < 4; a++)
#pragma unroll
        for (int b = 0; b < 4; b++)
#pragma unroll
            for (int c = 0; c < 4; c++) { acc1[a][b][c] = 0.f; acc2[a][b][c] = 0.f; }

    for (int kt = 0; kt < KSTEPS; kt++) {
        CP_WAIT2();
        __syncthreads();

        uint32_t sbase = st0 + (kt & 3) * STAGE_B;
        uint32_t sA1 = sbase, sA2 = sbase + MAT_B;
        uint32_t sB1 = sbase + 2 * MAT_B, sB2 = sbase + 3 * MAT_B;
#pragma unroll
        for (int k16 = 0; k16 < 2; k16++) {
            uint32_t a1[4][4], a2[4][4];
#pragma unroll
            for (int mi = 0; mi < 4; mi++) {
                uint32_t ad = SW64((uint32_t)(
                    (wm * 64 + mi * 16 + (lane & 15)) * 64
                    + k16 * 32 + (lane >> 4) * 16));
                ldsm_x4(a1[mi], sA1 + ad);
                ldsm_x4(a2[mi], sA2 + ad);
            }
            uint32_t b1[2][4], b2[2][4];
#pragma unroll
            for (int jj = 0; jj < 2; jj++) {
                uint32_t bd = SW64((uint32_t)(
                    (wn * 32 + jj * 16 + ((lane >> 4) << 3) + (lane & 7)) * 64
                    + k16 * 32 + (((lane >> 3) & 1) << 4)));
                ldsm_x4(b1[jj], sB1 + bd);
                ldsm_x4(b2[jj], sB2 + bd);
            }
            // term-major: T1 then T2; acc reuse distance 16 MMAs
#pragma unroll
            for (int mi = 0; mi < 4; mi++)
#pragma unroll
                for (int jj = 0; jj < 2; jj++)
#pragma unroll
                    for (int s = 0; s < 2; s++)
                        mma16816(acc1[mi][jj * 2 + s], a1[mi], &b1[jj][s * 2]);
#pragma unroll
            for (int mi = 0; mi < 4; mi++)
#pragma unroll
                for (int jj = 0; jj < 2; jj++)
#pragma unroll
                    for (int s = 0; s < 2; s++)
                        mma16816(acc2[mi][jj * 2 + s], a2[mi], &b2[jj][s * 2]);
        }

        __syncthreads();
        int nxt = kt + 3;
        if (nxt < KSTEPS) fill(nxt & 3, nxt);
        CP_COMMIT();
    }

    // epilogue: y = (T1*(31/32) + 32*T2) * rowfactor
#pragma unroll
    for (int mi = 0; mi < 4; mi++) {
        int r0 = wm * 64 + mi * 16 + (lane >> 2);
        float f0 = s_fr[r0], f1 = s_fr[r0 + 8];
        size_t o0 = (size_t)(mbase + r0) * HDIM + n0;
#pragma unroll
        for (int n8 = 0; n8 < 4; n8++) {
            int c = wn * 32 + n8 * 8 + (lane & 3) * 2;
            float y00 = (acc1[mi][n8][0] * 0.96875f + 32.f * acc2[mi][n8][0]) * f0;
            float y01 = (acc1[mi][n8][1] * 0.96875f + 32.f * acc2[mi][n8][1]) * f0;
            float y10 = (acc1[mi][n8][2] * 0.96875f + 32.f * acc2[mi][n8][2]) * f1;
            float y11 = (acc1[mi][n8][3] * 0.96875f + 32.f * acc2[mi][n8][3]) * f1;
            *(float2*)(g_ybuf + o0 + c) = make_float2(y00, y01);
            *(float2*)(g_ybuf + o0 + (size_t)8 * HDIM + c) = make_float2(y10, y11);
        }
    }
}

// ============================================================================
// K6: combine — out[t] = ybuf[slot0(t)] + ybuf[slot1(t)]
// ============================================================================
__global__ void moe_combine_kernel(float* __restrict__ out) {
    int i = blockIdx.x * blockDim.x + threadIdx.x;
    int t  = i >> 9;
    int h4 = i & 511;
    int s0 = g_tok_slot[2 * t + 0];
    int s1 = g_tok_slot[2 * t + 1];
    float4 a = *(const float4*)(g_ybuf + (size_t)s0 * HDIM + h4 * 4);
    float4 b = *(const float4*)(g_ybuf + (size_t)s1 * HDIM + h4 * 4);
    float4 o;
    o.x = a.x + b.x; o.y = a.y + b.y; o.z = a.z + b.z; o.w = a.w + b.w;
    ((float4*)out)[i] = o;
}

// ============================================================================
// Launch
// ============================================================================
extern "C" void kernel_launch(void* const* d_in, const int* in_sizes, int n_in,
                              void* d_out, int out_size) {
    const float* x  = (const float*)d_in[0];   // hidden_states [T, H]
    const float* gw = (const float*)d_in[1];   // gate_w [E, H]
    const float* ew = (const float*)d_in[2];   // expert_w [E, H, H]
    float* out    = (float*)d_out;             // [T, H]
    float* logits = out + (size_t)T_TOK * HDIM;

    cudaFuncSetAttribute(moe_gemm_kernel,
                         cudaFuncAttributeMaxDynamicSharedMemorySize, SMEM_DYN);

    moe_init_kernel<<<1, 32>>>();
    moe_router_kernel<<<(T_TOK * 32) / 256, 256>>>(x, gw, logits);
    moe_scan_kernel<<<1, 32>>>();
    moe_assign_kernel<<<T_TOK / 256, 256>>>();
    moe_convert_kernel<<<XBLK + WBLK, 256>>>(x, ew);
    moe_gemm_kernel<<<dim3(16, MAX_TILES), 256, SMEM_DYN>>>();
    moe_combine_kernel<<<(T_TOK * (HDIM / 4)) / 256, 256>>>(out);
}

// round 9
// speedup vs baseline: 4.1841x; 1.4188x over previous
#include <cuda_runtime.h>
#include <cuda_fp16.h>
#include <cstdint>

// ============================================================================
// Problem constants
// ============================================================================
#define T_TOK   8192          // B*S tokens
#define HDIM    2048
#define NEXP    8
#define NSLOTS  17408         // 2*T + 8*128 padding
#define MAX_TILES 136
#define KCAT    4096          // merged K: [xh | u] / [wh | 32v]
#define KSTEPS  128           // KCAT / 32 per k-step

// ============================================================================
// PTX helpers — family-portable only (mma.sync / ldmatrix / cp.async)
// ============================================================================
__device__ __forceinline__ uint32_t smem_to_u32(const void* p) {
    uint32_t a;
    asm("{ .reg .u64 t; cvta.to.shared.u64 t, %1; cvt.u32.u64 %0, t; }"
        : "=r"(a) : "l"(p));
    return a;
}

#define CP_ASYNC16(smem, gmem) \
    asm volatile("cp.async.cg.shared.global [%0], [%1], 16;" \
        :: "r"(smem), "l"(gmem))
#define CP_COMMIT() asm volatile("cp.async.commit_group;" ::: "memory")
#define CP_WAIT2()  asm volatile("cp.async.wait_group 2;" ::: "memory")

__device__ __forceinline__ void ldsm_x4(uint32_t* r, uint32_t addr) {
    asm volatile("ldmatrix.sync.aligned.m8n8.x4.shared.b16 {%0,%1,%2,%3}, [%4];"
        : "=r"(r[0]), "=r"(r[1]), "=r"(r[2]), "=r"(r[3]) : "r"(addr));
}

// m16n8k16 fp16 HMMA, fp32 accumulate
__device__ __forceinline__ void mma16816(float* d, const uint32_t* a,
                                         const uint32_t* b) {
    asm volatile(
        "mma.sync.aligned.m16n8k16.row.col.f32.f16.f16.f32 "
        "{%0,%1,%2,%3}, {%4,%5,%6,%7}, {%8,%9}, {%0,%1,%2,%3};"
        : "+f"(d[0]), "+f"(d[1]), "+f"(d[2]), "+f"(d[3])
        : "r"(a[0]), "r"(a[1]), "r"(a[2]), "r"(a[3]), "r"(b[0]), "r"(b[1]));
}

// SW64 swizzle: XOR byte-offset bits[5:4] with bits[8:7] (row bits for 64B rows)
#define SW64(off) ((off) ^ (((off) >> 3) & 0x30))

// ============================================================================
// Device scratch
// ============================================================================
__device__ int    g_count[NEXP];
__device__ int    g_cursor[NEXP];
__device__ int    g_base[NEXP];
__device__ int    g_tile_expert[MAX_TILES];
__device__ int    g_tile_mbase[MAX_TILES];
__device__ int    g_num_tiles;
__device__ int    g_topi[T_TOK * 2];
__device__ float  g_topw[T_TOK * 2];
__device__ int    g_slot_token[NSLOTS];    // zero-init; stale values stay in
__device__ float  g_slot_w[NSLOTS];        //   [0,T) so always a valid index
__device__ int    g_tok_slot[T_TOK * 2];

__device__ __half g_xc[(size_t)NSLOTS * KCAT];             // 139 MB [xh | u]
__device__ __half g_wc[(size_t)NEXP * HDIM * KCAT];        // 134 MB [wh | 32v]
__device__ float  g_ybuf[(size_t)NSLOTS * HDIM];           // 143 MB

// ============================================================================
// K0: reset counters
// ============================================================================
__global__ void moe_init_kernel() {
    int tid = threadIdx.x;
    if (tid < NEXP) { g_count[tid] = 0; g_cursor[tid] = 0; }
}

// ============================================================================
// K1: router — logits + top-2 normalized weights. One warp per token.
// ============================================================================
__global__ void moe_router_kernel(const float* __restrict__ x,
                                  const float* __restrict__ gw,
                                  float* __restrict__ logits_out) {
    int warp = (blockIdx.x * blockDim.x + threadIdx.x) >> 5;
    int lane = threadIdx.x & 31;
    if (warp >= T_TOK) return;
    const float4* xr = (const float4*)(x + (size_t)warp * HDIM);
    float acc[NEXP];
#pragma unroll
    for (int e = 0; e < NEXP; e++) acc[e] = 0.f;
    for (int i = lane; i < HDIM / 4; i += 32) {
        float4 xv = xr[i];
#pragma unroll
        for (int e = 0; e < NEXP; e++) {
            float4 gv = ((const float4*)(gw + e * HDIM))[i];
            acc[e] += xv.x * gv.x + xv.y * gv.y + xv.z * gv.z + xv.w * gv.w;
        }
    }
#pragma unroll
    for (int e = 0; e < NEXP; e++)
#pragma unroll
        for (int off = 16; off; off >>= 1)
            acc[e] += __shfl_xor_sync(0xFFFFFFFFu, acc[e], off);
    if (lane == 0) {
#pragma unroll
        for (int e = 0; e < NEXP; e++) logits_out[warp * NEXP + e] = acc[e];
        int i1 = 0; float l1 = acc[0];
#pragma unroll
        for (int e = 1; e < NEXP; e++) if (acc[e] > l1) { l1 = acc[e]; i1 = e; }
        int i2 = -1; float l2 = -3.4e38f;
#pragma unroll
        for (int e = 0; e < NEXP; e++)
            if (e != i1 && acc[e] > l2) { l2 = acc[e]; i2 = e; }
        float ex = expf(l2 - l1);
        float w1 = 1.0f / (1.0f + ex);
        float w2 = ex / (1.0f + ex);
        g_topi[warp * 2 + 0] = i1;  g_topw[warp * 2 + 0] = w1;
        g_topi[warp * 2 + 1] = i2;  g_topw[warp * 2 + 1] = w2;
        atomicAdd(&g_count[i1], 1);
        atomicAdd(&g_count[i2], 1);
    }
}

// ============================================================================
// K2: serial scan — padded slot bases + tile map
// ============================================================================
__global__ void moe_scan_kernel() {
    if (threadIdx.x == 0 && blockIdx.x == 0) {
        int run = 0, nt = 0;
        for (int e = 0; e < NEXP; e++) {
            g_base[e] = run;
            int c = g_count[e];
            int tiles = (c + 127) >> 7;
            for (int t = 0; t < tiles; t++) {
                g_tile_expert[nt] = e;
                g_tile_mbase[nt]  = run + t * 128;
                nt++;
            }
            run += tiles << 7;
        }
        g_num_tiles = nt;
    }
}

// ============================================================================
// K3: scatter tokens into per-expert slot lists
// ============================================================================
__global__ void moe_assign_kernel() {
    int t = blockIdx.x * blockDim.x + threadIdx.x;
    if (t >= T_TOK) return;
#pragma unroll
    for (int k = 0; k < 2; k++) {
        int e = g_topi[t * 2 + k];
        int pos = atomicAdd(&g_cursor[e], 1);
        int slot = g_base[e] + pos;
        g_slot_token[slot] = t;
        g_slot_w[slot] = g_topw[t * 2 + k];
        g_tok_slot[t * 2 + k] = slot;
    }
}

// ============================================================================
// K4: split-convert (Ootomo, merged-K layout).
//   A row (4096): [ xh = fp16(x) | u = fp16(xh/32 + (x-xh)) ]
//   B row (4096): [ wh = fp16(64w) | 32*fp16(wh/32 + (64w-wh)) ]  (32x exact)
// ============================================================================
#define XBLK (NSLOTS * 512 / 256)                 // 34816
#define WBLK (NEXP * HDIM * HDIM / 4 / 256)       // 32768

__device__ __forceinline__ void split2(float a, float b, uint32_t& h,
                                       uint32_t& u, float post) {
    __half2 hh = __floats2half2_rn(a, b);
    float2 hf = __half22float2(hh);
    __half2 uu = __floats2half2_rn((hf.x * 0.03125f + (a - hf.x)) * post,
                                   (hf.y * 0.03125f + (b - hf.y)) * post);
    h = *(uint32_t*)&hh;
    u = *(uint32_t*)&uu;
}

__global__ void moe_convert_kernel(const float* __restrict__ x,
                                   const float* __restrict__ ew) {
    if (blockIdx.x < XBLK) {
        int i = blockIdx.x * 256 + threadIdx.x;
        int slot = i >> 9;
        int j = i & 511;
        int tok = g_slot_token[slot];
        float4 vv = *(const float4*)(x + (size_t)tok * HDIM + j * 4);
        uint32_t h0, u0, h1, u1;
        split2(vv.x, vv.y, h0, u0, 1.0f);
        split2(vv.z, vv.w, h1, u1, 1.0f);
        size_t rb = (size_t)slot * (KCAT / 4);          // uint2 units per row
        ((uint2*)g_xc)[rb + j]       = make_uint2(h0, h1);
        ((uint2*)g_xc)[rb + 512 + j] = make_uint2(u0, u1);
    } else {
        size_t i = (size_t)(blockIdx.x - XBLK) * 256 + threadIdx.x;
        int row = (int)(i >> 9);                        // e*HDIM + n
        int j = (int)(i & 511);
        float4 vv = ((const float4*)ew)[i];
        uint32_t h0, u0, h1, u1;
        // post=32 scales the correction term exactly (power of 2 in fp16)
        split2(vv.x * 64.f, vv.y * 64.f, h0, u0, 32.0f);
        split2(vv.z * 64.f, vv.w * 64.f, h1, u1, 32.0f);
        size_t rb = (size_t)row * (KCAT / 4);
        ((uint2*)g_wc)[rb + j]       = make_uint2(h0, h1);
        ((uint2*)g_wc)[rb + 512 + j] = make_uint2(u0, u1);
    }
}

// ============================================================================
// K5: grouped GEMM — 128x128xK4096 merged Ootomo, single fp32 acc set,
// 4 warps (2x2 grid, 64x64 warp tile), 2 CTAs/SM, 4-stage cp.async, SW64.
// Mid-loop: acc *= 31/32 (fp32-exact) between the xh*wh and u*32v halves.
// y = acc * slotw / 64
// Stage mapping invariant: chunk c lives in stage (c & 3) — prologue fills
// chunks 0,1,2 into stages 0,1,2; mainloop refills chunk kt+3 into stage
// (kt+3)&3 (the stage consumed in iteration kt-1, ordered by syncthreads).
// ============================================================================
#define MAT_B     8192                        // 128 rows x 64B
#define STAGE_B   (2 * MAT_B)                 // 16384 (A, B)
#define NSTAGE    4
#define SMEM_DYN  (1024 + NSTAGE * STAGE_B)   // 66560 B -> 2 CTAs/SM

__global__ void __launch_bounds__(128, 2)
moe_gemm_kernel() {
    int tile = blockIdx.y;
    if (tile >= g_num_tiles) return;
    int n0    = blockIdx.x * 128;
    int e     = g_tile_expert[tile];
    int mbase = g_tile_mbase[tile];

    extern __shared__ char dsm[];
    float* s_fr = (float*)dsm;                // 128: slotw/64 per row
    uint32_t st0 = smem_to_u32(dsm) + 1024;

    int tid = threadIdx.x, lane = tid & 31, wid = tid >> 5;
    int wm = wid >> 1, wn = wid & 1;          // 2x2 grid, warp 64(M)x64(N)

    if (tid < 128) s_fr[tid] = g_slot_w[mbase + tid] * (1.0f / 64.0f);

    const __half* Ag = g_xc + (size_t)mbase * KCAT;
    const __half* Bg = g_wc + ((size_t)e * HDIM + n0) * KCAT;

    // fill stage: 1024 x 16B chunks over 128 threads (8 per thread)
    auto fill = [&](int stage, int kt) {
        uint32_t sbase = st0 + stage * STAGE_B;
        int k0 = kt * 32;
#pragma unroll
        for (int i = 0; i < 8; i++) {
            int cid = tid + i * 128;
            int mat = cid >> 9;               // 0=A, 1=B
            int win = cid & 511;
            int rr  = win >> 2;
            int cc  = win & 3;
            const __half* gp = (mat ? Bg : Ag) + (size_t)rr * KCAT + k0 + cc * 8;
            uint32_t sm = sbase + mat * MAT_B
                        + SW64((uint32_t)(rr * 64 + cc * 16));
            CP_ASYNC16(sm, gp);
        }
    };

    fill(0, 0); CP_COMMIT();
    fill(1, 1); CP_COMMIT();
    fill(2, 2); CP_COMMIT();

    float acc[4][8][4];
#pragma unroll
    for (int a = 0; a < 4; a++)
#pragma unroll
        for (int b = 0; b < 8; b++)
#pragma unroll
            for (int c = 0; c < 4; c++) acc[a][b][c] = 0.f;

    for (int kt = 0; kt < KSTEPS; kt++) {
        // between halves: acc = T1 -> scale by 31/32 (fp32-exact cancellation)
        if (kt == KSTEPS / 2) {
#pragma unroll
            for (int a = 0; a < 4; a++)
#pragma unroll
                for (int b = 0; b < 8; b++)
#pragma unroll
                    for (int c = 0; c < 4; c++) acc[a][b][c] *= 0.96875f;
        }
        CP_WAIT2();
        __syncthreads();

        uint32_t sbase = st0 + (kt & 3) * STAGE_B;
        uint32_t sA = sbase, sB = sbase + MAT_B;
#pragma unroll
        for (int k16 = 0; k16 < 2; k16++) {
            uint32_t af[4][4];
#pragma unroll
            for (int mi = 0; mi < 4; mi++) {
                uint32_t ad = SW64((uint32_t)(
                    (wm * 64 + mi * 16 + (lane & 15)) * 64
                    + k16 * 32 + (lane >> 4) * 16));
                ldsm_x4(af[mi], sA + ad);
            }
            uint32_t bf[4][4];
#pragma unroll
            for (int jj = 0; jj < 4; jj++) {
                uint32_t bd = SW64((uint32_t)(
                    (wn * 64 + jj * 16 + ((lane >> 4) << 3) + (lane & 7)) * 64
                    + k16 * 32 + (((lane >> 3) & 1) << 4)));
                ldsm_x4(bf[jj], sB + bd);
            }
            // 32 HMMAs per k16, acc reuse distance 32
#pragma unroll
            for (int mi = 0; mi < 4; mi++)
#pragma unroll
                for (int jj = 0; jj < 4; jj++)
#pragma unroll
                    for (int s = 0; s < 2; s++)
                        mma16816(acc[mi][jj * 2 + s], af[mi], &bf[jj][s * 2]);
        }

        __syncthreads();
        int nxt = kt + 3;
        if (nxt < KSTEPS) fill(nxt & 3, nxt);  // stage = chunk & 3 (invariant)
        CP_COMMIT();
    }

    // epilogue: y = acc * slotw/64
#pragma unroll
    for (int mi = 0; mi < 4; mi++) {
        int r0 = wm * 64 + mi * 16 + (lane >> 2);
        float f0 = s_fr[r0], f1 = s_fr[r0 + 8];
        size_t o0 = (size_t)(mbase + r0) * HDIM + n0;
#pragma unroll
        for (int n8 = 0; n8 < 8; n8++) {
            int c = wn * 64 + n8 * 8 + (lane & 3) * 2;
            *(float2*)(g_ybuf + o0 + c) =
                make_float2(acc[mi][n8][0] * f0, acc[mi][n8][1] * f0);
            *(float2*)(g_ybuf + o0 + (size_t)8 * HDIM + c) =
                make_float2(acc[mi][n8][2] * f1, acc[mi][n8][3] * f1);
        }
    }
}

// ============================================================================
// K6: combine — out[t] = ybuf[slot0(t)] + ybuf[slot1(t)]
// ============================================================================
__global__ void moe_combine_kernel(float* __restrict__ out) {
    int i = blockIdx.x * blockDim.x + threadIdx.x;
    int t  = i >> 9;
    int h4 = i & 511;
    int s0 = g_tok_slot[2 * t + 0];
    int s1 = g_tok_slot[2 * t + 1];
    float4 a = *(const float4*)(g_ybuf + (size_t)s0 * HDIM + h4 * 4);
    float4 b = *(const float4*)(g_ybuf + (size_t)s1 * HDIM + h4 * 4);
    float4 o;
    o.x = a.x + b.x; o.y = a.y + b.y; o.z = a.z + b.z; o.w = a.w + b.w;
    ((float4*)out)[i] = o;
}

// ============================================================================
// Launch
// ============================================================================
extern "C" void kernel_launch(void* const* d_in, const int* in_sizes, int n_in,
                              void* d_out, int out_size) {
    const float* x  = (const float*)d_in[0];   // hidden_states [T, H]
    const float* gw = (const float*)d_in[1];   // gate_w [E, H]
    const float* ew = (const float*)d_in[2];   // expert_w [E, H, H]
    float* out    = (float*)d_out;             // [T, H]
    float* logits = out + (size_t)T_TOK * HDIM;

    cudaFuncSetAttribute(moe_gemm_kernel,
                         cudaFuncAttributeMaxDynamicSharedMemorySize, SMEM_DYN);

    moe_init_kernel<<<1, 32>>>();
    moe_router_kernel<<<(T_TOK * 32) / 256, 256>>>(x, gw, logits);
    moe_scan_kernel<<<1, 32>>>();
    moe_assign_kernel<<<T_TOK / 256, 256>>>();
    moe_convert_kernel<<<XBLK + WBLK, 256>>>(x, ew);
    moe_gemm_kernel<<<dim3(16, MAX_TILES), 128, SMEM_DYN>>>();
    moe_combine_kernel<<<(T_TOK * (HDIM / 4)) / 256, 256>>>(out);
}

// round 10
// speedup vs baseline: 4.3667x; 1.0436x over previous
#include <cuda_runtime.h>
#include <cuda_fp16.h>
#include <cstdint>

// ============================================================================
// Problem constants
// ============================================================================
#define T_TOK   8192          // B*S tokens
#define HDIM    2048
#define NEXP    8
#define NSLOTS  17408         // 2*T + 8*128 padding
#define MAX_TILES 136
#define KCAT    4096          // merged K: [xh | u] / [wh | 32v]
#define KSTEPS  128           // KCAT / 32 per k-step

// ============================================================================
// PTX helpers — family-portable only (mma.sync / ldmatrix / cp.async)
// ============================================================================
__device__ __forceinline__ uint32_t smem_to_u32(const void* p) {
    uint32_t a;
    asm("{ .reg .u64 t; cvta.to.shared.u64 t, %1; cvt.u32.u64 %0, t; }"
        : "=r"(a) : "l"(p));
    return a;
}

#define CP_ASYNC16(smem, gmem) \
    asm volatile("cp.async.cg.shared.global [%0], [%1], 16;" \
        :: "r"(smem), "l"(gmem))
#define CP_COMMIT() asm volatile("cp.async.commit_group;" ::: "memory")
#define CP_WAIT2()  asm volatile("cp.async.wait_group 2;" ::: "memory")

__device__ __forceinline__ void ldsm_x4(uint32_t* r, uint32_t addr) {
    asm volatile("ldmatrix.sync.aligned.m8n8.x4.shared.b16 {%0,%1,%2,%3}, [%4];"
        : "=r"(r[0]), "=r"(r[1]), "=r"(r[2]), "=r"(r[3]) : "r"(addr));
}

// m16n8k16 fp16 HMMA, fp32 accumulate
__device__ __forceinline__ void mma16816(float* d, const uint32_t* a,
                                         const uint32_t* b) {
    asm volatile(
        "mma.sync.aligned.m16n8k16.row.col.f32.f16.f16.f32 "
        "{%0,%1,%2,%3}, {%4,%5,%6,%7}, {%8,%9}, {%0,%1,%2,%3};"
        : "+f"(d[0]), "+f"(d[1]), "+f"(d[2]), "+f"(d[3])
        : "r"(a[0]), "r"(a[1]), "r"(a[2]), "r"(a[3]), "r"(b[0]), "r"(b[1]));
}

// SW64 swizzle: XOR byte-offset bits[5:4] with bits[8:7] (row bits for 64B rows)
#define SW64(off) ((off) ^ (((off) >> 3) & 0x30))

// ============================================================================
// Device scratch
// ============================================================================
__device__ int    g_count[NEXP];
__device__ int    g_cursor[NEXP];
__device__ int    g_base[NEXP];
__device__ int    g_tile_expert[MAX_TILES];
__device__ int    g_tile_mbase[MAX_TILES];
__device__ int    g_num_tiles;
__device__ int    g_topi[T_TOK * 2];
__device__ float  g_topw[T_TOK * 2];
__device__ int    g_slot_token[NSLOTS];    // zero-init; stale values stay in
__device__ float  g_slot_w[NSLOTS];        //   [0,T) so always a valid index
__device__ int    g_tok_slot[T_TOK * 2];

__device__ __half g_xc[(size_t)T_TOK * KCAT];              // 67 MB [xh | u], per TOKEN
__device__ __half g_wc[(size_t)NEXP * HDIM * KCAT];        // 134 MB [wh | 32v]
__device__ float  g_ybuf[(size_t)NSLOTS * HDIM];           // 143 MB

// ============================================================================
// K0: reset counters
// ============================================================================
__global__ void moe_init_kernel() {
    int tid = threadIdx.x;
    if (tid < NEXP) { g_count[tid] = 0; g_cursor[tid] = 0; }
}

// ============================================================================
// K1: router — logits + top-2 normalized weights. One warp per token.
// ============================================================================
__global__ void moe_router_kernel(const float* __restrict__ x,
                                  const float* __restrict__ gw,
                                  float* __restrict__ logits_out) {
    int warp = (blockIdx.x * blockDim.x + threadIdx.x) >> 5;
    int lane = threadIdx.x & 31;
    if (warp >= T_TOK) return;
    const float4* xr = (const float4*)(x + (size_t)warp * HDIM);
    float acc[NEXP];
#pragma unroll
    for (int e = 0; e < NEXP; e++) acc[e] = 0.f;
    for (int i = lane; i < HDIM / 4; i += 32) {
        float4 xv = xr[i];
#pragma unroll
        for (int e = 0; e < NEXP; e++) {
            float4 gv = ((const float4*)(gw + e * HDIM))[i];
            acc[e] += xv.x * gv.x + xv.y * gv.y + xv.z * gv.z + xv.w * gv.w;
        }
    }
#pragma unroll
    for (int e = 0; e < NEXP; e++)
#pragma unroll
        for (int off = 16; off; off >>= 1)
            acc[e] += __shfl_xor_sync(0xFFFFFFFFu, acc[e], off);
    if (lane == 0) {
#pragma unroll
        for (int e = 0; e < NEXP; e++) logits_out[warp * NEXP + e] = acc[e];
        int i1 = 0; float l1 = acc[0];
#pragma unroll
        for (int e = 1; e < NEXP; e++) if (acc[e] > l1) { l1 = acc[e]; i1 = e; }
        int i2 = -1; float l2 = -3.4e38f;
#pragma unroll
        for (int e = 0; e < NEXP; e++)
            if (e != i1 && acc[e] > l2) { l2 = acc[e]; i2 = e; }
        float ex = expf(l2 - l1);
        float w1 = 1.0f / (1.0f + ex);
        float w2 = ex / (1.0f + ex);
        g_topi[warp * 2 + 0] = i1;  g_topw[warp * 2 + 0] = w1;
        g_topi[warp * 2 + 1] = i2;  g_topw[warp * 2 + 1] = w2;
        atomicAdd(&g_count[i1], 1);
        atomicAdd(&g_count[i2], 1);
    }
}

// ============================================================================
// K2: serial scan — padded slot bases + tile map
// ============================================================================
__global__ void moe_scan_kernel() {
    if (threadIdx.x == 0 && blockIdx.x == 0) {
        int run = 0, nt = 0;
        for (int e = 0; e < NEXP; e++) {
            g_base[e] = run;
            int c = g_count[e];
            int tiles = (c + 127) >> 7;
            for (int t = 0; t < tiles; t++) {
                g_tile_expert[nt] = e;
                g_tile_mbase[nt]  = run + t * 128;
                nt++;
            }
            run += tiles << 7;
        }
        g_num_tiles = nt;
    }
}

// ============================================================================
// K3: scatter tokens into per-expert slot lists
// ============================================================================
__global__ void moe_assign_kernel() {
    int t = blockIdx.x * blockDim.x + threadIdx.x;
    if (t >= T_TOK) return;
#pragma unroll
    for (int k = 0; k < 2; k++) {
        int e = g_topi[t * 2 + k];
        int pos = atomicAdd(&g_cursor[e], 1);
        int slot = g_base[e] + pos;
        g_slot_token[slot] = t;
        g_slot_w[slot] = g_topw[t * 2 + k];
        g_tok_slot[t * 2 + k] = slot;
    }
}

// ============================================================================
// K4: split-convert (Ootomo, merged-K layout). x stored per TOKEN (GEMM
// gathers rows through slot_token at fill time).
//   A row (4096): [ xh = fp16(x) | u = fp16(xh/32 + (x-xh)) ]
//   B row (4096): [ wh = fp16(64w) | 32*fp16(wh/32 + (64w-wh)) ]  (32x exact)
// ============================================================================
#define XBLK (T_TOK * 512 / 256)                  // 16384
#define WBLK (NEXP * HDIM * HDIM / 4 / 256)       // 32768

__device__ __forceinline__ void split2(float a, float b, uint32_t& h,
                                       uint32_t& u, float post) {
    __half2 hh = __floats2half2_rn(a, b);
    float2 hf = __half22float2(hh);
    __half2 uu = __floats2half2_rn((hf.x * 0.03125f + (a - hf.x)) * post,
                                   (hf.y * 0.03125f + (b - hf.y)) * post);
    h = *(uint32_t*)&hh;
    u = *(uint32_t*)&uu;
}

__global__ void moe_convert_kernel(const float* __restrict__ x,
                                   const float* __restrict__ ew) {
    if (blockIdx.x < XBLK) {
        int i = blockIdx.x * 256 + threadIdx.x;
        int tok = i >> 9;
        int j = i & 511;
        float4 vv = ((const float4*)x)[(size_t)tok * 512 + j];
        uint32_t h0, u0, h1, u1;
        split2(vv.x, vv.y, h0, u0, 1.0f);
        split2(vv.z, vv.w, h1, u1, 1.0f);
        size_t rb = (size_t)tok * (KCAT / 4);           // uint2 units per row
        ((uint2*)g_xc)[rb + j]       = make_uint2(h0, h1);
        ((uint2*)g_xc)[rb + 512 + j] = make_uint2(u0, u1);
    } else {
        size_t i = (size_t)(blockIdx.x - XBLK) * 256 + threadIdx.x;
        int row = (int)(i >> 9);                        // e*HDIM + n
        int j = (int)(i & 511);
        float4 vv = ((const float4*)ew)[i];
        uint32_t h0, u0, h1, u1;
        // post=32 scales the correction term exactly (power of 2 in fp16)
        split2(vv.x * 64.f, vv.y * 64.f, h0, u0, 32.0f);
        split2(vv.z * 64.f, vv.w * 64.f, h1, u1, 32.0f);
        size_t rb = (size_t)row * (KCAT / 4);
        ((uint2*)g_wc)[rb + j]       = make_uint2(h0, h1);
        ((uint2*)g_wc)[rb + 512 + j] = make_uint2(u0, u1);
    }
}

// ============================================================================
// K5: grouped GEMM — 128x128xK4096 merged Ootomo, single fp32 acc set,
// 4 warps (2x2 grid, 64x64 warp tile), 2 CTAs/SM, 4-stage cp.async, SW64.
// Single __syncthreads per k-step: the top sync proves all warps finished
// iteration kt-1, so refilling stage (kt+3)&3 (read in kt-1) right after it
// is safe; cp.async then overlaps the MMA block.
// A rows gathered per-token via s_token; 8 gmem pointers precomputed.
// Mid-loop: acc *= 31/32 (fp32-exact) between the xh*wh and u*32v halves.
// ============================================================================
#define MAT_B     8192                        // 128 rows x 64B
#define STAGE_B   (2 * MAT_B)                 // 16384 (A, B)
#define NSTAGE    4
#define SMEM_DYN  (1024 + NSTAGE * STAGE_B)   // 66560 B -> 2 CTAs/SM

__global__ void __launch_bounds__(128, 2)
moe_gemm_kernel() {
    int tile = blockIdx.y;
    if (tile >= g_num_tiles) return;
    int n0    = blockIdx.x * 128;
    int e     = g_tile_expert[tile];
    int mbase = g_tile_mbase[tile];

    extern __shared__ char dsm[];
    float* s_fr    = (float*)dsm;             // 128: slotw/64 per row
    int*   s_token = (int*)(dsm + 512);       // 128: token per row
    uint32_t st0 = smem_to_u32(dsm) + 1024;

    int tid = threadIdx.x, lane = tid & 31, wid = tid >> 5;
    int wm = wid >> 1, wn = wid & 1;          // 2x2 grid, warp 64(M)x64(N)

    if (tid < 128) {
        s_fr[tid]    = g_slot_w[mbase + tid] * (1.0f / 64.0f);
        s_token[tid] = g_slot_token[mbase + tid];
    }
    __syncthreads();

    const __half* Bg = g_wc + ((size_t)e * HDIM + n0) * KCAT;

    // precompute per-thread fill pointers (8 chunks: 4 A via token gather, 4 B)
    const __half* gsrc[8];
    uint32_t sdst[8];
#pragma unroll
    for (int i = 0; i < 8; i++) {
        int cid = tid + i * 128;
        int mat = cid >> 9;                   // 0=A, 1=B
        int win = cid & 511;
        int rr  = win >> 2;
        int cc  = win & 3;
        if (mat == 0) {
            int tok = s_token[rr];
            gsrc[i] = g_xc + (size_t)tok * KCAT + cc * 8;
        } else {
            gsrc[i] = Bg + (size_t)rr * KCAT + cc * 8;
        }
        sdst[i] = st0 + mat * MAT_B + SW64((uint32_t)(rr * 64 + cc * 16));
    }

    auto fill = [&](int stage, int kt) {
        uint32_t so = (uint32_t)(stage * STAGE_B);
        int k0 = kt * 32;
#pragma unroll
        for (int i = 0; i < 8; i++)
            CP_ASYNC16(sdst[i] + so, gsrc[i] + k0);
    };

    fill(0, 0); CP_COMMIT();
    fill(1, 1); CP_COMMIT();
    fill(2, 2); CP_COMMIT();

    float acc[4][8][4];
#pragma unroll
    for (int a = 0; a < 4; a++)
#pragma unroll
        for (int b = 0; b < 8; b++)
#pragma unroll
            for (int c = 0; c < 4; c++) acc[a][b][c] = 0.f;

    for (int kt = 0; kt < KSTEPS; kt++) {
        // between halves: acc = T1 -> scale by 31/32 (fp32-exact cancellation)
        if (kt == KSTEPS / 2) {
#pragma unroll
            for (int a = 0; a < 4; a++)
#pragma unroll
                for (int b = 0; b < 8; b++)
#pragma unroll
                    for (int c = 0; c < 4; c++) acc[a][b][c] *= 0.96875f;
        }
        CP_WAIT2();
        __syncthreads();                      // single sync per k-step

        int nxt = kt + 3;                     // stage (kt+3)&3 was read in kt-1
        if (nxt < KSTEPS) fill(nxt & 3, nxt);
        CP_COMMIT();

        uint32_t sbase = st0 + (kt & 3) * STAGE_B;
        uint32_t sA = sbase, sB = sbase + MAT_B;
#pragma unroll
        for (int k16 = 0; k16 < 2; k16++) {
            uint32_t af[4][4];
#pragma unroll
            for (int mi = 0; mi < 4; mi++) {
                uint32_t ad = SW64((uint32_t)(
                    (wm * 64 + mi * 16 + (lane & 15)) * 64
                    + k16 * 32 + (lane >> 4) * 16));
                ldsm_x4(af[mi], sA + ad);
            }
            uint32_t bf[4][4];
#pragma unroll
            for (int jj = 0; jj < 4; jj++) {
                uint32_t bd = SW64((uint32_t)(
                    (wn * 64 + jj * 16 + ((lane >> 4) << 3) + (lane & 7)) * 64
                    + k16 * 32 + (((lane >> 3) & 1) << 4)));
                ldsm_x4(bf[jj], sB + bd);
            }
            // 32 HMMAs per k16, acc reuse distance 32
#pragma unroll
            for (int mi = 0; mi < 4; mi++)
#pragma unroll
                for (int jj = 0; jj < 4; jj++)
#pragma unroll
                    for (int s = 0; s < 2; s++)
                        mma16816(acc[mi][jj * 2 + s], af[mi], &bf[jj][s * 2]);
        }
    }

    // epilogue: y = acc * slotw/64
#pragma unroll
    for (int mi = 0; mi < 4; mi++) {
        int r0 = wm * 64 + mi * 16 + (lane >> 2);
        float f0 = s_fr[r0], f1 = s_fr[r0 + 8];
        size_t o0 = (size_t)(mbase + r0) * HDIM + n0;
#pragma unroll
        for (int n8 = 0; n8 < 8; n8++) {
            int c = wn * 64 + n8 * 8 + (lane & 3) * 2;
            *(float2*)(g_ybuf + o0 + c) =
                make_float2(acc[mi][n8][0] * f0, acc[mi][n8][1] * f0);
            *(float2*)(g_ybuf + o0 + (size_t)8 * HDIM + c) =
                make_float2(acc[mi][n8][2] * f1, acc[mi][n8][3] * f1);
        }
    }
}

// ============================================================================
// K6: combine — out[t] = ybuf[slot0(t)] + ybuf[slot1(t)]
// ============================================================================
__global__ void moe_combine_kernel(float* __restrict__ out) {
    int i = blockIdx.x * blockDim.x + threadIdx.x;
    int t  = i >> 9;
    int h4 = i & 511;
    int s0 = g_tok_slot[2 * t + 0];
    int s1 = g_tok_slot[2 * t + 1];
    float4 a = *(const float4*)(g_ybuf + (size_t)s0 * HDIM + h4 * 4);
    float4 b = *(const float4*)(g_ybuf + (size_t)s1 * HDIM + h4 * 4);
    float4 o;
    o.x = a.x + b.x; o.y = a.y + b.y; o.z = a.z + b.z; o.w = a.w + b.w;
    ((float4*)out)[i] = o;
}

// ============================================================================
// Launch
// ============================================================================
extern "C" void kernel_launch(void* const* d_in, const int* in_sizes, int n_in,
                              void* d_out, int out_size) {
    const float* x  = (const float*)d_in[0];   // hidden_states [T, H]
    const float* gw = (const float*)d_in[1];   // gate_w [E, H]
    const float* ew = (const float*)d_in[2];   // expert_w [E, H, H]
    float* out    = (float*)d_out;             // [T, H]
    float* logits = out + (size_t)T_TOK * HDIM;

    cudaFuncSetAttribute(moe_gemm_kernel,
                         cudaFuncAttributeMaxDynamicSharedMemorySize, SMEM_DYN);

    moe_init_kernel<<<1, 32>>>();
    moe_router_kernel<<<(T_TOK * 32) / 256, 256>>>(x, gw, logits);
    moe_scan_kernel<<<1, 32>>>();
    moe_assign_kernel<<<T_TOK / 256, 256>>>();
    moe_convert_kernel<<<XBLK + WBLK, 256>>>(x, ew);
    moe_gemm_kernel<<<dim3(16, MAX_TILES), 128, SMEM_DYN>>>();
    moe_combine_kernel<<<(T_TOK * (HDIM / 4)) / 256, 256>>>(out);
}